// round 12
// baseline (speedup 1.0000x reference)
#include <cuda_runtime.h>

// ScorePredictor: 3x DistMult edge scoring.
// score[e] = clip( sum_d head[src[e],d] * rel[d] * tail[dst[e],d], 0, 1 )
//
// SINGLE stream only — multi-stream fork/join inside the captured graph
// regressed 273us -> 422/462us in rounds 10/11.
//
// Pipeline: counting sort of each edge list by one endpoint, then 3 score
// kernels run SEQUENTIALLY (phase separation = L2 residency; concurrent
// scores thrash the 240MB union working set).
//   L1 hist   (all 3 phases, atomicAdd/RED, no zero pass needed: bins are
//              zero-initialized at load and re-zeroed by each score kernel's
//              prefix blocks after its scatter consumed them)
//   L2 scan   (3 blocks, one per phase)
//   L3 scatter (4 edges per thread -> 4 independent atomic chains)
//   L4-6 score phase 0,1,2  (+ prefix blocks re-zero that phase's hist)
//
// Score kernel (R7/R9 winner, unchanged): warp handles 8 consecutive SORTED
// edges, k-chunk outer loop; rel chunk loaded once per k, head chunk
// (pre-multiplied by rel) reloaded only on key change, all 8 independent
// tail loads batched (MLP=8/warp). EPW=8 fits regs at launch_bounds(256,3).

#define D_DIM 2048
#define WARPS_PER_BLOCK 8
#define THREADS_PER_BLOCK (WARPS_PER_BLOCK * 32)
#define EDGES_PER_WARP 8
#define EDGES_PER_BLOCK (WARPS_PER_BLOCK * EDGES_PER_WARP)

#define MAX_BINS 32768
#define MAX_E    131072

__device__ int  g_hist[3][MAX_BINS];   // zero-initialized at module load
__device__ int4 g_edge[3][MAX_E];      // (key, other, edge, pad)

// ---------------- sort: hist / scan / scatter ----------------

// Batched histogram over all three phases. No zero pass: bins are zero at
// call entry (module init on first call; score-kernel prefixes afterwards).
__global__ void hist_all(const int* __restrict__ k0,   // ddi_src
                         const int* __restrict__ k1,   // dpi_dst
                         const int* __restrict__ k2,   // ppi_src
                         int E) {
    int i = blockIdx.x * blockDim.x + threadIdx.x;
    if (i >= 3 * E) return;
    int p = i / E, e = i - p * E;
    int key = (p == 0) ? __ldg(k0 + e) : (p == 1) ? __ldg(k1 + e) : __ldg(k2 + e);
    atomicAdd(&g_hist[p][key], 1);     // no return use -> RED fast path
}

__global__ void scan_all(int nbins0, int nbins12) {
    const int p = blockIdx.x;           // one block per phase
    const int nbins = (p == 0) ? nbins0 : nbins12;
    int* h = g_hist[p];
    const int T = 1024;
    const int t = threadIdx.x;
    __shared__ int buf[2][1024];

    int chunk = (nbins + T - 1) / T;
    int start = t * chunk;
    int end   = min(start + chunk, nbins);

    int s = 0;
    for (int i = start; i < end; ++i) s += h[i];
    buf[0][t] = s;
    __syncthreads();

    int src = 0;
    for (int off = 1; off < T; off <<= 1) {
        int v = buf[src][t];
        if (t >= off) v += buf[src][t - off];
        buf[src ^ 1][t] = v;
        src ^= 1;
        __syncthreads();
    }

    int base = (t == 0) ? 0 : buf[src][t - 1];
    int run = base;
    for (int i = start; i < end; ++i) {
        int v = h[i];
        h[i] = run;
        run += v;
    }
}

// 4 edges per thread -> 4 independent atomicAdd-return chains (ILP).
// Requires E % 4 == 0 (E = 100000).
__global__ void scatter_all(const int* __restrict__ s0, const int* __restrict__ d0,
                            const int* __restrict__ s1, const int* __restrict__ d1,
                            const int* __restrict__ s2, const int* __restrict__ d2,
                            int E) {
    const int q = E >> 2;                       // edges per thread-slot
    int i = blockIdx.x * blockDim.x + threadIdx.x;
    if (i >= 3 * q) return;
    int p = i / q, r = i - p * q;

    const int* ks = (p == 0) ? s0 : (p == 1) ? d1 : s2;   // grouping key
    const int* os = (p == 0) ? d0 : (p == 1) ? s1 : d2;   // other endpoint

    #pragma unroll
    for (int j = 0; j < 4; ++j) {
        int e = r + j * q;
        int k = __ldg(ks + e);
        int o = __ldg(os + e);
        int pos = atomicAdd(&g_hist[p][k], 1);
        g_edge[p][pos] = make_int4(k, o, e, 0);
    }
}

// ---------------- score ----------------

// First ZBLK blocks re-zero this phase's histogram (restores the zero
// invariant for the next call); remaining blocks score edges.
template <int P>
__global__ __launch_bounds__(THREADS_PER_BLOCK, 3)
void score_p(
    const float* __restrict__ xs,    // sorted-side table (heads)
    const float* __restrict__ xr,    // random-side table (tails)
    const float* __restrict__ rel,
    float*       __restrict__ o,
    int E, int nbins, int zblk)
{
    if (blockIdx.x < (unsigned)zblk) {
        int i = blockIdx.x * blockDim.x + threadIdx.x;
        if (i < nbins) g_hist[P][i] = 0;
        return;
    }

    const int4* recs = g_edge[P];

    const int warp = threadIdx.x >> 5;
    const int lane = threadIdx.x & 31;
    const int base = ((blockIdx.x - zblk) * WARPS_PER_BLOCK + warp) * EDGES_PER_WARP;
    if (base >= E) return;

    // Lanes 0..7 fetch packed edge records; broadcast via shuffles.
    int pos = base + lane;
    if (pos >= E) pos = E - 1;              // duplicate last edge (same output)
    int my_s = 0, my_d = 0, my_edge = 0;
    if (lane < EDGES_PER_WARP) {
        int4 r = __ldg(recs + pos);
        my_s = r.x; my_d = r.y; my_edge = r.z;
    }

    int s[EDGES_PER_WARP], dI[EDGES_PER_WARP];
    #pragma unroll
    for (int e = 0; e < EDGES_PER_WARP; ++e) {
        s[e]  = __shfl_sync(0xffffffffu, my_s, e);
        dI[e] = __shfl_sync(0xffffffffu, my_d, e);
    }

    float acc[EDGES_PER_WARP];
    #pragma unroll
    for (int e = 0; e < EDGES_PER_WARP; ++e) acc[e] = 0.0f;

    // 16 k-chunks of float4 per lane. Batch all 8 independent tail loads
    // before the FMA block so ptxas issues them back-to-back (MLP=8).
    #pragma unroll 2
    for (int k = 0; k < D_DIM / (32 * 4); ++k) {
        const int idx = (k * 32 + lane) * 4;

        float4 t[EDGES_PER_WARP];
        #pragma unroll
        for (int e = 0; e < EDGES_PER_WARP; ++e)
            t[e] = __ldg(reinterpret_cast<const float4*>(
                       xr + (size_t)dI[e] * D_DIM + idx));

        const float4 r = __ldg(reinterpret_cast<const float4*>(rel + idx));

        float4 hr;   // head chunk pre-multiplied by rel; reload on key change
        #pragma unroll
        for (int e = 0; e < EDGES_PER_WARP; ++e) {
            if (e == 0 || s[e] != s[e - 1]) {   // warp-uniform branch
                float4 h = __ldg(reinterpret_cast<const float4*>(
                               xs + (size_t)s[e] * D_DIM + idx));
                hr.x = h.x * r.x; hr.y = h.y * r.y;
                hr.z = h.z * r.z; hr.w = h.w * r.w;
            }
            acc[e] = fmaf(hr.x, t[e].x, acc[e]);
            acc[e] = fmaf(hr.y, t[e].y, acc[e]);
            acc[e] = fmaf(hr.z, t[e].z, acc[e]);
            acc[e] = fmaf(hr.w, t[e].w, acc[e]);
        }
    }

    // Reduce and write each edge's score.
    #pragma unroll
    for (int e = 0; e < EDGES_PER_WARP; ++e) {
        float a = acc[e];
        #pragma unroll
        for (int off = 16; off > 0; off >>= 1)
            a += __shfl_xor_sync(0xffffffffu, a, off);
        const int edge_e = __shfl_sync(0xffffffffu, my_edge, e);
        if (lane == 0)
            o[edge_e] = fminf(fmaxf(a, 0.0f), 1.0f);
    }
}

// ---------------- launch ----------------

extern "C" void kernel_launch(void* const* d_in, const int* in_sizes, int n_in,
                              void* d_out, int out_size)
{
    const float* x_drug  = (const float*)d_in[0];
    const float* x_prot  = (const float*)d_in[1];
    const float* rel_ddi = (const float*)d_in[2];
    const float* rel_dpi = (const float*)d_in[3];
    const int*   ddi_src = (const int*)d_in[4];
    const int*   ddi_dst = (const int*)d_in[5];
    const int*   dpi_src = (const int*)d_in[6];
    const int*   dpi_dst = (const int*)d_in[7];
    const int*   ppi_src = (const int*)d_in[8];
    const int*   ppi_dst = (const int*)d_in[9];
    float* out = (float*)d_out;

    const int E      = in_sizes[4];
    const int N_DRUG = in_sizes[0] / D_DIM;
    const int N_PROT = in_sizes[1] / D_DIM;

    // Sort (bins are zero at entry: module init / prior score-kernel prefixes).
    hist_all<<<(3 * E + 255) / 256, 256>>>(ddi_src, dpi_dst, ppi_src, E);
    scan_all<<<3, 1024>>>(N_DRUG, N_PROT);
    scatter_all<<<(3 * (E / 4) + 255) / 256, 256>>>(
        ddi_src, ddi_dst, dpi_src, dpi_dst, ppi_src, ppi_dst, E);

    const int bpp    = (E + EDGES_PER_BLOCK - 1) / EDGES_PER_BLOCK;
    const int zdrug  = (N_DRUG + THREADS_PER_BLOCK - 1) / THREADS_PER_BLOCK;
    const int zprot  = (N_PROT + THREADS_PER_BLOCK - 1) / THREADS_PER_BLOCK;

    // Scores: strictly sequential (phase separation = L2 residency).
    score_p<0><<<bpp + zdrug, THREADS_PER_BLOCK>>>(
        x_drug, x_drug, rel_ddi, out,         E, N_DRUG, zdrug);
    score_p<1><<<bpp + zprot, THREADS_PER_BLOCK>>>(
        x_prot, x_drug, rel_dpi, out + E,     E, N_PROT, zprot);
    score_p<2><<<bpp + zprot, THREADS_PER_BLOCK>>>(
        x_prot, x_prot, rel_dpi, out + 2 * E, E, N_PROT, zprot);
}

// round 13
// speedup vs baseline: 1.7016x; 1.7016x over previous
#include <cuda_runtime.h>

// ScorePredictor: 3x DistMult edge scoring.
// score[e] = clip( sum_d head[src[e],d] * rel[d] * tail[dst[e],d], 0, 1 )
//
// This is the R9 winner (273us), re-anchored after 3 regressions:
//  - single stream ONLY (multi-stream fork/join in capture: 422/462us)
//  - EPW=8 (EPW=16 spills: 367us)
//  - no score-kernel grafts / no scatter reordering (R12: 467us)
// Sole delta vs R9: zero_hist clears only the used bins (50k vs 98k).
//
// Pipeline: counting sort of each edge list by one endpoint (zero/hist/scan/
// scatter -> packed int4 records), then ONE fused score kernel; phases run
// sequentially inside it (blockIdx-ordered) preserving L2 phase separation.
// Score: warp handles 8 consecutive SORTED edges, k-chunk outer loop; rel
// chunk loaded once per k, head chunk (pre-multiplied by rel) reloaded only
// on key change, all 8 independent tail loads batched (MLP=8/warp).

#define D_DIM 2048
#define WARPS_PER_BLOCK 8
#define THREADS_PER_BLOCK (WARPS_PER_BLOCK * 32)
#define EDGES_PER_WARP 8
#define EDGES_PER_BLOCK (WARPS_PER_BLOCK * EDGES_PER_WARP)

#define MAX_BINS 32768
#define MAX_E    131072

__device__ int  g_hist[3][MAX_BINS];
__device__ int4 g_edge[3][MAX_E];    // (key, other, edge, pad)

// ---------------- sort: zero / hist / scan / scatter ----------------

// Zero only the bins each phase actually uses: [0]=n0, [1]=n12, [2]=n12.
__global__ void zero_hist_kernel(int n0, int n12) {
    int i = blockIdx.x * blockDim.x + threadIdx.x;
    if (i < n0)                 g_hist[0][i] = 0;
    else if (i < n0 + n12)      g_hist[1][i - n0] = 0;
    else if (i < n0 + 2 * n12)  g_hist[2][i - n0 - n12] = 0;
}

__global__ void hist_kernel(const int* __restrict__ k0,   // ddi_src
                            const int* __restrict__ k1,   // dpi_dst
                            const int* __restrict__ k2,   // ppi_src
                            int E) {
    int i = blockIdx.x * blockDim.x + threadIdx.x;
    if (i >= 3 * E) return;
    int p = i / E, e = i - p * E;
    int key = (p == 0) ? __ldg(k0 + e) : (p == 1) ? __ldg(k1 + e) : __ldg(k2 + e);
    atomicAdd(&g_hist[p][key], 1);
}

__global__ void scan_kernel(int nbins0, int nbins12) {
    const int p = blockIdx.x;           // one block per phase
    const int nbins = (p == 0) ? nbins0 : nbins12;
    int* h = g_hist[p];
    const int T = 1024;
    const int t = threadIdx.x;
    __shared__ int buf[2][1024];

    int chunk = (nbins + T - 1) / T;
    int start = t * chunk;
    int end   = min(start + chunk, nbins);

    int s = 0;
    for (int i = start; i < end; ++i) s += h[i];
    buf[0][t] = s;
    __syncthreads();

    int src = 0;
    for (int off = 1; off < T; off <<= 1) {
        int v = buf[src][t];
        if (t >= off) v += buf[src][t - off];
        buf[src ^ 1][t] = v;
        src ^= 1;
        __syncthreads();
    }

    int base = (t == 0) ? 0 : buf[src][t - 1];
    int run = base;
    for (int i = start; i < end; ++i) {
        int v = h[i];
        h[i] = run;
        run += v;
    }
}

__global__ void scatter_kernel(const int* __restrict__ s0, const int* __restrict__ d0,
                               const int* __restrict__ s1, const int* __restrict__ d1,
                               const int* __restrict__ s2, const int* __restrict__ d2,
                               int E) {
    int i = blockIdx.x * blockDim.x + threadIdx.x;
    if (i >= 3 * E) return;
    int p = i / E, e = i - p * E;
    // grouping key: ddi by src, dpi by dst (protein side), ppi by src
    int key, other;
    if (p == 0)      { key = __ldg(s0 + e); other = __ldg(d0 + e); }
    else if (p == 1) { key = __ldg(d1 + e); other = __ldg(s1 + e); }
    else             { key = __ldg(s2 + e); other = __ldg(d2 + e); }
    int pos = atomicAdd(&g_hist[p][key], 1);
    g_edge[p][pos] = make_int4(key, other, e, 0);
}

// ---------------- fused score ----------------

__global__ __launch_bounds__(THREADS_PER_BLOCK, 3)
void edge_score_fused(
    const float* __restrict__ x_drug,
    const float* __restrict__ x_prot,
    const float* __restrict__ rel_ddi,
    const float* __restrict__ rel_dpi,
    float*       __restrict__ out,
    int E, int blocks_per_phase)
{
    const int phase = blockIdx.x / blocks_per_phase;
    const int blk   = blockIdx.x - phase * blocks_per_phase;

    // Table binding: sorted-side table (heads), random-side table (tails).
    const float* xs;  const float* xr;  const float* rel;  float* o;
    if (phase == 0)      { xs = x_drug; xr = x_drug; rel = rel_ddi; o = out; }
    else if (phase == 1) { xs = x_prot; xr = x_drug; rel = rel_dpi; o = out + E; }
    else                 { xs = x_prot; xr = x_prot; rel = rel_dpi; o = out + 2 * E; }
    const int4* recs = g_edge[phase];

    const int warp = threadIdx.x >> 5;
    const int lane = threadIdx.x & 31;
    const int base = (blk * WARPS_PER_BLOCK + warp) * EDGES_PER_WARP;
    if (base >= E) return;

    // Lanes 0..7 fetch packed edge records; broadcast via shuffles.
    int pos = base + lane;
    if (pos >= E) pos = E - 1;              // duplicate last edge (same output)
    int my_s = 0, my_d = 0, my_edge = 0;
    if (lane < EDGES_PER_WARP) {
        int4 r = __ldg(recs + pos);
        my_s = r.x; my_d = r.y; my_edge = r.z;
    }

    int s[EDGES_PER_WARP], dI[EDGES_PER_WARP];
    #pragma unroll
    for (int e = 0; e < EDGES_PER_WARP; ++e) {
        s[e]  = __shfl_sync(0xffffffffu, my_s, e);
        dI[e] = __shfl_sync(0xffffffffu, my_d, e);
    }

    float acc[EDGES_PER_WARP];
    #pragma unroll
    for (int e = 0; e < EDGES_PER_WARP; ++e) acc[e] = 0.0f;

    // 16 k-chunks of float4 per lane. Batch all 8 independent tail loads
    // before the FMA block so ptxas issues them back-to-back (MLP=8).
    #pragma unroll 2
    for (int k = 0; k < D_DIM / (32 * 4); ++k) {
        const int idx = (k * 32 + lane) * 4;

        float4 t[EDGES_PER_WARP];
        #pragma unroll
        for (int e = 0; e < EDGES_PER_WARP; ++e)
            t[e] = __ldg(reinterpret_cast<const float4*>(
                       xr + (size_t)dI[e] * D_DIM + idx));

        const float4 r = __ldg(reinterpret_cast<const float4*>(rel + idx));

        float4 hr;   // head chunk pre-multiplied by rel; reload on key change
        #pragma unroll
        for (int e = 0; e < EDGES_PER_WARP; ++e) {
            if (e == 0 || s[e] != s[e - 1]) {   // warp-uniform branch
                float4 h = __ldg(reinterpret_cast<const float4*>(
                               xs + (size_t)s[e] * D_DIM + idx));
                hr.x = h.x * r.x; hr.y = h.y * r.y;
                hr.z = h.z * r.z; hr.w = h.w * r.w;
            }
            acc[e] = fmaf(hr.x, t[e].x, acc[e]);
            acc[e] = fmaf(hr.y, t[e].y, acc[e]);
            acc[e] = fmaf(hr.z, t[e].z, acc[e]);
            acc[e] = fmaf(hr.w, t[e].w, acc[e]);
        }
    }

    // Reduce and write each edge's score.
    #pragma unroll
    for (int e = 0; e < EDGES_PER_WARP; ++e) {
        float a = acc[e];
        #pragma unroll
        for (int off = 16; off > 0; off >>= 1)
            a += __shfl_xor_sync(0xffffffffu, a, off);
        const int edge_e = __shfl_sync(0xffffffffu, my_edge, e);
        if (lane == 0)
            o[edge_e] = fminf(fmaxf(a, 0.0f), 1.0f);
    }
}

// ---------------- launch ----------------

extern "C" void kernel_launch(void* const* d_in, const int* in_sizes, int n_in,
                              void* d_out, int out_size)
{
    const float* x_drug  = (const float*)d_in[0];
    const float* x_prot  = (const float*)d_in[1];
    const float* rel_ddi = (const float*)d_in[2];
    const float* rel_dpi = (const float*)d_in[3];
    const int*   ddi_src = (const int*)d_in[4];
    const int*   ddi_dst = (const int*)d_in[5];
    const int*   dpi_src = (const int*)d_in[6];
    const int*   dpi_dst = (const int*)d_in[7];
    const int*   ppi_src = (const int*)d_in[8];
    const int*   ppi_dst = (const int*)d_in[9];
    float* out = (float*)d_out;

    const int E      = in_sizes[4];
    const int N_DRUG = in_sizes[0] / D_DIM;
    const int N_PROT = in_sizes[1] / D_DIM;

    const int nz = N_DRUG + 2 * N_PROT;
    zero_hist_kernel<<<(nz + 255) / 256, 256>>>(N_DRUG, N_PROT);
    hist_kernel<<<(3 * E + 255) / 256, 256>>>(ddi_src, dpi_dst, ppi_src, E);
    scan_kernel<<<3, 1024>>>(N_DRUG, N_PROT);
    scatter_kernel<<<(3 * E + 255) / 256, 256>>>(
        ddi_src, ddi_dst, dpi_src, dpi_dst, ppi_src, ppi_dst, E);

    const int bpp = (E + EDGES_PER_BLOCK - 1) / EDGES_PER_BLOCK;

    edge_score_fused<<<3 * bpp, THREADS_PER_BLOCK>>>(
        x_drug, x_prot, rel_ddi, rel_dpi, out, E, bpp);
}

// round 14
// speedup vs baseline: 1.7124x; 1.0063x over previous
#include <cuda_runtime.h>

// ScorePredictor: 3x DistMult edge scoring.
// score[e] = clip( sum_d head[src[e],d] * rel[d] * tail[dst[e],d], 0, 1 )
//
// R13 anchor (274.6us; score kernel at the LTS roofline) with ONE change:
// scatter processes 4 consecutive edges per thread -> 4 independent
// atomicAdd-return chains (it was ATOMG-latency bound: occ 74%, issue 9%).
// Established invariants (violations all regressed 30-70%):
//  - single stream only; NO multi-stream fork/join in capture
//  - ONE fused score launch (split-score variants all slow)
//  - EPW=8 at __launch_bounds__(256,3) (EPW=16 spills)
//  - score kernel body untouched

#define D_DIM 2048
#define WARPS_PER_BLOCK 8
#define THREADS_PER_BLOCK (WARPS_PER_BLOCK * 32)
#define EDGES_PER_WARP 8
#define EDGES_PER_BLOCK (WARPS_PER_BLOCK * EDGES_PER_WARP)

#define MAX_BINS 32768
#define MAX_E    131072

__device__ int  g_hist[3][MAX_BINS];
__device__ int4 g_edge[3][MAX_E];    // (key, other, edge, pad)

// ---------------- sort: zero / hist / scan / scatter ----------------

// Zero only the bins each phase actually uses: [0]=n0, [1]=n12, [2]=n12.
__global__ void zero_hist_kernel(int n0, int n12) {
    int i = blockIdx.x * blockDim.x + threadIdx.x;
    if (i < n0)                 g_hist[0][i] = 0;
    else if (i < n0 + n12)      g_hist[1][i - n0] = 0;
    else if (i < n0 + 2 * n12)  g_hist[2][i - n0 - n12] = 0;
}

__global__ void hist_kernel(const int* __restrict__ k0,   // ddi_src
                            const int* __restrict__ k1,   // dpi_dst
                            const int* __restrict__ k2,   // ppi_src
                            int E) {
    int i = blockIdx.x * blockDim.x + threadIdx.x;
    if (i >= 3 * E) return;
    int p = i / E, e = i - p * E;
    int key = (p == 0) ? __ldg(k0 + e) : (p == 1) ? __ldg(k1 + e) : __ldg(k2 + e);
    atomicAdd(&g_hist[p][key], 1);
}

__global__ void scan_kernel(int nbins0, int nbins12) {
    const int p = blockIdx.x;           // one block per phase
    const int nbins = (p == 0) ? nbins0 : nbins12;
    int* h = g_hist[p];
    const int T = 1024;
    const int t = threadIdx.x;
    __shared__ int buf[2][1024];

    int chunk = (nbins + T - 1) / T;
    int start = t * chunk;
    int end   = min(start + chunk, nbins);

    int s = 0;
    for (int i = start; i < end; ++i) s += h[i];
    buf[0][t] = s;
    __syncthreads();

    int src = 0;
    for (int off = 1; off < T; off <<= 1) {
        int v = buf[src][t];
        if (t >= off) v += buf[src][t - off];
        buf[src ^ 1][t] = v;
        src ^= 1;
        __syncthreads();
    }

    int base = (t == 0) ? 0 : buf[src][t - 1];
    int run = base;
    for (int i = start; i < end; ++i) {
        int v = h[i];
        h[i] = run;
        run += v;
    }
}

// 4 CONSECUTIVE edges per thread -> 4 independent ATOMG chains (MLP=4);
// consecutive edges have random keys so chains rarely collide. Contiguous
// assignment keeps intra-bin record order close to the original.
__global__ void scatter_kernel(const int* __restrict__ s0, const int* __restrict__ d0,
                               const int* __restrict__ s1, const int* __restrict__ d1,
                               const int* __restrict__ s2, const int* __restrict__ d2,
                               int E) {
    const int q = (E + 3) >> 2;                 // thread-slots per phase
    int i = blockIdx.x * blockDim.x + threadIdx.x;
    if (i >= 3 * q) return;
    int p = i / q, r = i - p * q;

    const int* ks = (p == 0) ? s0 : (p == 1) ? d1 : s2;   // grouping key
    const int* os = (p == 0) ? d0 : (p == 1) ? s1 : d2;   // other endpoint

    const int e0 = r * 4;
    #pragma unroll
    for (int j = 0; j < 4; ++j) {
        int e = e0 + j;
        if (e >= E) break;
        int k = __ldg(ks + e);
        int o = __ldg(os + e);
        int pos = atomicAdd(&g_hist[p][k], 1);
        g_edge[p][pos] = make_int4(k, o, e, 0);
    }
}

// ---------------- fused score ----------------

__global__ __launch_bounds__(THREADS_PER_BLOCK, 3)
void edge_score_fused(
    const float* __restrict__ x_drug,
    const float* __restrict__ x_prot,
    const float* __restrict__ rel_ddi,
    const float* __restrict__ rel_dpi,
    float*       __restrict__ out,
    int E, int blocks_per_phase)
{
    const int phase = blockIdx.x / blocks_per_phase;
    const int blk   = blockIdx.x - phase * blocks_per_phase;

    // Table binding: sorted-side table (heads), random-side table (tails).
    const float* xs;  const float* xr;  const float* rel;  float* o;
    if (phase == 0)      { xs = x_drug; xr = x_drug; rel = rel_ddi; o = out; }
    else if (phase == 1) { xs = x_prot; xr = x_drug; rel = rel_dpi; o = out + E; }
    else                 { xs = x_prot; xr = x_prot; rel = rel_dpi; o = out + 2 * E; }
    const int4* recs = g_edge[phase];

    const int warp = threadIdx.x >> 5;
    const int lane = threadIdx.x & 31;
    const int base = (blk * WARPS_PER_BLOCK + warp) * EDGES_PER_WARP;
    if (base >= E) return;

    // Lanes 0..7 fetch packed edge records; broadcast via shuffles.
    int pos = base + lane;
    if (pos >= E) pos = E - 1;              // duplicate last edge (same output)
    int my_s = 0, my_d = 0, my_edge = 0;
    if (lane < EDGES_PER_WARP) {
        int4 r = __ldg(recs + pos);
        my_s = r.x; my_d = r.y; my_edge = r.z;
    }

    int s[EDGES_PER_WARP], dI[EDGES_PER_WARP];
    #pragma unroll
    for (int e = 0; e < EDGES_PER_WARP; ++e) {
        s[e]  = __shfl_sync(0xffffffffu, my_s, e);
        dI[e] = __shfl_sync(0xffffffffu, my_d, e);
    }

    float acc[EDGES_PER_WARP];
    #pragma unroll
    for (int e = 0; e < EDGES_PER_WARP; ++e) acc[e] = 0.0f;

    // 16 k-chunks of float4 per lane. Batch all 8 independent tail loads
    // before the FMA block so ptxas issues them back-to-back (MLP=8).
    #pragma unroll 2
    for (int k = 0; k < D_DIM / (32 * 4); ++k) {
        const int idx = (k * 32 + lane) * 4;

        float4 t[EDGES_PER_WARP];
        #pragma unroll
        for (int e = 0; e < EDGES_PER_WARP; ++e)
            t[e] = __ldg(reinterpret_cast<const float4*>(
                       xr + (size_t)dI[e] * D_DIM + idx));

        const float4 r = __ldg(reinterpret_cast<const float4*>(rel + idx));

        float4 hr;   // head chunk pre-multiplied by rel; reload on key change
        #pragma unroll
        for (int e = 0; e < EDGES_PER_WARP; ++e) {
            if (e == 0 || s[e] != s[e - 1]) {   // warp-uniform branch
                float4 h = __ldg(reinterpret_cast<const float4*>(
                               xs + (size_t)s[e] * D_DIM + idx));
                hr.x = h.x * r.x; hr.y = h.y * r.y;
                hr.z = h.z * r.z; hr.w = h.w * r.w;
            }
            acc[e] = fmaf(hr.x, t[e].x, acc[e]);
            acc[e] = fmaf(hr.y, t[e].y, acc[e]);
            acc[e] = fmaf(hr.z, t[e].z, acc[e]);
            acc[e] = fmaf(hr.w, t[e].w, acc[e]);
        }
    }

    // Reduce and write each edge's score.
    #pragma unroll
    for (int e = 0; e < EDGES_PER_WARP; ++e) {
        float a = acc[e];
        #pragma unroll
        for (int off = 16; off > 0; off >>= 1)
            a += __shfl_xor_sync(0xffffffffu, a, off);
        const int edge_e = __shfl_sync(0xffffffffu, my_edge, e);
        if (lane == 0)
            o[edge_e] = fminf(fmaxf(a, 0.0f), 1.0f);
    }
}

// ---------------- launch ----------------

extern "C" void kernel_launch(void* const* d_in, const int* in_sizes, int n_in,
                              void* d_out, int out_size)
{
    const float* x_drug  = (const float*)d_in[0];
    const float* x_prot  = (const float*)d_in[1];
    const float* rel_ddi = (const float*)d_in[2];
    const float* rel_dpi = (const float*)d_in[3];
    const int*   ddi_src = (const int*)d_in[4];
    const int*   ddi_dst = (const int*)d_in[5];
    const int*   dpi_src = (const int*)d_in[6];
    const int*   dpi_dst = (const int*)d_in[7];
    const int*   ppi_src = (const int*)d_in[8];
    const int*   ppi_dst = (const int*)d_in[9];
    float* out = (float*)d_out;

    const int E      = in_sizes[4];
    const int N_DRUG = in_sizes[0] / D_DIM;
    const int N_PROT = in_sizes[1] / D_DIM;

    const int nz = N_DRUG + 2 * N_PROT;
    zero_hist_kernel<<<(nz + 255) / 256, 256>>>(N_DRUG, N_PROT);
    hist_kernel<<<(3 * E + 255) / 256, 256>>>(ddi_src, dpi_dst, ppi_src, E);
    scan_kernel<<<3, 1024>>>(N_DRUG, N_PROT);

    const int q = (E + 3) / 4;
    scatter_kernel<<<(3 * q + 255) / 256, 256>>>(
        ddi_src, ddi_dst, dpi_src, dpi_dst, ppi_src, ppi_dst, E);

    const int bpp = (E + EDGES_PER_BLOCK - 1) / EDGES_PER_BLOCK;

    edge_score_fused<<<3 * bpp, THREADS_PER_BLOCK>>>(
        x_drug, x_prot, rel_ddi, rel_dpi, out, E, bpp);
}